// round 1
// baseline (speedup 1.0000x reference)
#include <cuda_runtime.h>

// CondConv2d: B=16, CIN=32, H=W=256, COUT=32, K=3x3 same-pad, 8 experts.
// out[b,co,h,w] = bias_b[co] + sum_{ci,kh,kw} Wb[co,ci,kh,kw] * xpad[b,ci,h+kh-1,w+kw-1]
// Wb = routing[b] @ expert_weight ; bias_b = routing[b] @ expert_bias.

#define B_   16
#define CIN_ 32
#define HW_  256
#define COUT_ 32
#define NEXP 8
#define NPARAM (COUT_ * CIN_ * 9)   // 9216

// Scratch: per-sample weights in [ci][tap][co] layout (tap = kh*3+kw), plus bias.
__device__ float g_w[B_ * NPARAM];
__device__ float g_bias[B_ * COUT_];

// ---------------------------------------------------------------------------
// Kernel 1: mix expert weights per sample, permute to [ci][tap][co].
// ---------------------------------------------------------------------------
__global__ void condconv_prep_kernel(const float* __restrict__ rw,
                                     const float* __restrict__ ew,
                                     const float* __restrict__ eb) {
    int b = blockIdx.x;
    int tid = threadIdx.x;
    float r[NEXP];
#pragma unroll
    for (int e = 0; e < NEXP; e++) r[e] = rw[b * NEXP + e];

    for (int idx = tid; idx < NPARAM; idx += blockDim.x) {
        // dest layout: idx = ci*288 + t*32 + co
        int ci = idx / 288;
        int rem = idx % 288;
        int t = rem >> 5;        // rem / 32
        int co = rem & 31;       // rem % 32
        int src = co * (CIN_ * 9) + ci * 9 + t;  // source: [co][ci][kh][kw]
        float s = 0.f;
#pragma unroll
        for (int e = 0; e < NEXP; e++) s += r[e] * ew[e * NPARAM + src];
        g_w[b * NPARAM + idx] = s;
    }
    if (tid < COUT_) {
        float s = 0.f;
#pragma unroll
        for (int e = 0; e < NEXP; e++) s += r[e] * eb[e * COUT_ + tid];
        g_bias[b * COUT_ + tid] = s;
    }
}

// ---------------------------------------------------------------------------
// Kernel 2: direct conv.
// Grid: (8, 16, 16) = (w-tiles, h-tiles, batch). Block: 256 threads.
// CTA computes a 16(h) x 32(w) output tile for ALL 32 couts of one batch.
// Thread: 2 adjacent-w pixels x 32 couts = 64 accumulators.
// cin processed in 4 chunks of 8 (smem: x-tile 8x18x36 + weights 8x9x32).
// ---------------------------------------------------------------------------
#define TILE_H 16
#define TILE_W 32
#define CCHUNK 8
#define XPITCH 36   // padded row pitch (floats) for the 34-wide halo row

__global__ __launch_bounds__(256, 2)
void condconv_conv_kernel(const float* __restrict__ x, float* __restrict__ out) {
    __shared__ float xs[CCHUNK * 18 * XPITCH];   // 20736 B
    __shared__ float ws[CCHUNK * 9 * COUT_];     //  9216 B
    __shared__ float bs[COUT_];

    const int b  = blockIdx.z;
    const int ty = blockIdx.y;   // h tile
    const int tx = blockIdx.x;   // w tile
    const int tid = threadIdx.x;
    const int px = tid & 15;     // w-pair index (covers w = 2*px, 2*px+1)
    const int py = tid >> 4;     // row in tile

    const int oh = ty * TILE_H + py;
    const int ow = tx * TILE_W + px * 2;

    const float* gw = g_w + b * NPARAM;
    if (tid < COUT_) bs[tid] = g_bias[b * COUT_ + tid];

    float acc[2 * COUT_];
#pragma unroll
    for (int i = 0; i < 2 * COUT_; i++) acc[i] = 0.f;

    const int ih0 = ty * TILE_H - 1;
    const int iw0 = tx * TILE_W - 1;

    for (int c0 = 0; c0 < CIN_; c0 += CCHUNK) {
        __syncthreads();  // protect smem reuse from previous chunk

        // --- stage weights for this cin chunk (already [ci][t][co] linear) ---
        for (int i = tid; i < CCHUNK * 9 * COUT_; i += 256)
            ws[i] = gw[c0 * 9 * COUT_ + i];

        // --- stage input tile 8 x 18 x 34 with zero halo ---
        for (int i = tid; i < CCHUNK * 18 * 34; i += 256) {
            int ci  = i / (18 * 34);
            int r2  = i % (18 * 34);
            int row = r2 / 34;
            int col = r2 % 34;
            int ih = ih0 + row;
            int iw = iw0 + col;
            float v = 0.f;
            if ((unsigned)ih < 256u && (unsigned)iw < 256u)
                v = x[(((size_t)b * CIN_ + (c0 + ci)) * HW_ + ih) * HW_ + iw];
            xs[ci * (18 * XPITCH) + row * XPITCH + col] = v;
        }
        __syncthreads();

        // --- compute ---
        for (int ci = 0; ci < CCHUNK; ci++) {
            const float* xrow = &xs[ci * (18 * XPITCH) + py * XPITCH + 2 * px];
            float rin[3][4];
#pragma unroll
            for (int kh = 0; kh < 3; kh++) {
                float2 a = *(const float2*)(xrow + kh * XPITCH);
                float2 c = *(const float2*)(xrow + kh * XPITCH + 2);
                rin[kh][0] = a.x; rin[kh][1] = a.y;
                rin[kh][2] = c.x; rin[kh][3] = c.y;
            }
            const float* wp = &ws[ci * 9 * COUT_];
#pragma unroll
            for (int t = 0; t < 9; t++) {
                const int kh = t / 3, kw = t % 3;
                const float i0 = rin[kh][kw];
                const float i1 = rin[kh][kw + 1];
#pragma unroll
                for (int co = 0; co < COUT_; co += 4) {
                    float4 w4 = *(const float4*)(wp + t * COUT_ + co);
                    acc[(co + 0) * 2]     += w4.x * i0;
                    acc[(co + 0) * 2 + 1] += w4.x * i1;
                    acc[(co + 1) * 2]     += w4.y * i0;
                    acc[(co + 1) * 2 + 1] += w4.y * i1;
                    acc[(co + 2) * 2]     += w4.z * i0;
                    acc[(co + 2) * 2 + 1] += w4.z * i1;
                    acc[(co + 3) * 2]     += w4.w * i0;
                    acc[(co + 3) * 2 + 1] += w4.w * i1;
                }
            }
        }
    }

    // --- epilogue: bias + store (float2, ow is even -> 8B aligned) ---
#pragma unroll
    for (int co = 0; co < COUT_; co++) {
        float2 v;
        v.x = acc[co * 2]     + bs[co];
        v.y = acc[co * 2 + 1] + bs[co];
        *(float2*)&out[(((size_t)b * COUT_ + co) * HW_ + oh) * HW_ + ow] = v;
    }
}

// ---------------------------------------------------------------------------
extern "C" void kernel_launch(void* const* d_in, const int* in_sizes, int n_in,
                              void* d_out, int out_size) {
    const float* x  = (const float*)d_in[0];
    const float* rw = (const float*)d_in[1];
    const float* ew = (const float*)d_in[2];
    const float* eb = (const float*)d_in[3];
    float* out = (float*)d_out;

    condconv_prep_kernel<<<B_, 256>>>(rw, ew, eb);

    dim3 grid(HW_ / TILE_W, HW_ / TILE_H, B_);
    condconv_conv_kernel<<<grid, 256>>>(x, out);
}

// round 2
// speedup vs baseline: 1.0125x; 1.0125x over previous
#include <cuda_runtime.h>

// CondConv2d: B=16, CIN=32, H=W=256, COUT=32, K=3x3 same-pad, 8 experts.
// Round 2: packed f32x2 FFMA (FFMA2) over adjacent-cout pairs.

#define B_   16
#define CIN_ 32
#define HW_  256
#define COUT_ 32
#define NEXP 8
#define NPARAM (COUT_ * CIN_ * 9)   // 9216

__device__ float g_w[B_ * NPARAM];
__device__ float g_bias[B_ * COUT_];

// ---- packed f32x2 helpers (Blackwell sm_103a) -------------------------------
#define DUP_F32X2(d, s)  asm("mov.b64 %0, {%1, %1};" : "=l"(d) : "r"(s))
#define FMA2(acc, a, b)  asm("fma.rn.f32x2 %0, %1, %2, %0;" : "+l"(acc) : "l"(a), "l"(b))
#define UNPACK2(lo, hi, p) asm("mov.b64 {%0, %1}, %2;" : "=f"(lo), "=f"(hi) : "l"(p))

// ---------------------------------------------------------------------------
// Kernel 1: mix expert weights per sample, permute to [ci][tap][co].
// ---------------------------------------------------------------------------
__global__ void condconv_prep_kernel(const float* __restrict__ rw,
                                     const float* __restrict__ ew,
                                     const float* __restrict__ eb) {
    int b = blockIdx.x;
    int tid = threadIdx.x;
    float r[NEXP];
#pragma unroll
    for (int e = 0; e < NEXP; e++) r[e] = rw[b * NEXP + e];

    for (int idx = tid; idx < NPARAM; idx += blockDim.x) {
        int ci = idx / 288;
        int rem = idx % 288;
        int t = rem >> 5;
        int co = rem & 31;
        int src = co * (CIN_ * 9) + ci * 9 + t;  // source: [co][ci][kh][kw]
        float s = 0.f;
#pragma unroll
        for (int e = 0; e < NEXP; e++) s += r[e] * ew[e * NPARAM + src];
        g_w[b * NPARAM + idx] = s;
    }
    if (tid < COUT_) {
        float s = 0.f;
#pragma unroll
        for (int e = 0; e < NEXP; e++) s += r[e] * eb[e * COUT_ + tid];
        g_bias[b * COUT_ + tid] = s;
    }
}

// ---------------------------------------------------------------------------
// Kernel 2: direct conv with FFMA2.
// Grid: (8, 16, 16). Block 256. CTA = 16h x 32w tile, all 32 couts, one batch.
// Thread: 2 adjacent-w pixels x 32 couts; accumulators packed as f32x2 over
// cout pairs so the weight operand is a natural float2 from smem.
// ---------------------------------------------------------------------------
#define TILE_H 16
#define TILE_W 32
#define CCHUNK 8
#define XPITCH 36

__global__ __launch_bounds__(256, 2)
void condconv_conv_kernel(const float* __restrict__ x, float* __restrict__ out) {
    __shared__ float xs[CCHUNK * 18 * XPITCH];   // 20736 B
    __shared__ float ws[CCHUNK * 9 * COUT_];     //  9216 B
    __shared__ float bs[COUT_];

    const int b  = blockIdx.z;
    const int ty = blockIdx.y;
    const int tx = blockIdx.x;
    const int tid = threadIdx.x;
    const int px = tid & 15;
    const int py = tid >> 4;

    const int oh = ty * TILE_H + py;
    const int ow = tx * TILE_W + px * 2;

    const float* gw = g_w + b * NPARAM;
    if (tid < COUT_) bs[tid] = g_bias[b * COUT_ + tid];

    // acc0[k]/acc1[k]: pixel 0 / pixel 1, cout pair (2k, 2k+1) packed f32x2
    unsigned long long acc0[16], acc1[16];
#pragma unroll
    for (int i = 0; i < 16; i++) { acc0[i] = 0ULL; acc1[i] = 0ULL; }

    const int ih0 = ty * TILE_H - 1;
    const int iw0 = tx * TILE_W - 1;

    for (int c0 = 0; c0 < CIN_; c0 += CCHUNK) {
        __syncthreads();

        for (int i = tid; i < CCHUNK * 9 * COUT_; i += 256)
            ws[i] = gw[c0 * 9 * COUT_ + i];

        for (int i = tid; i < CCHUNK * 18 * 34; i += 256) {
            int ci  = i / (18 * 34);
            int r2  = i % (18 * 34);
            int row = r2 / 34;
            int col = r2 % 34;
            int ih = ih0 + row;
            int iw = iw0 + col;
            float v = 0.f;
            if ((unsigned)ih < 256u && (unsigned)iw < 256u)
                v = x[(((size_t)b * CIN_ + (c0 + ci)) * HW_ + ih) * HW_ + iw];
            xs[ci * (18 * XPITCH) + row * XPITCH + col] = v;
        }
        __syncthreads();

#pragma unroll 1
        for (int ci = 0; ci < CCHUNK; ci++) {
            const float* xrow = &xs[ci * (18 * XPITCH) + py * XPITCH + 2 * px];
            float rin[3][4];
#pragma unroll
            for (int kh = 0; kh < 3; kh++) {
                float2 a = *(const float2*)(xrow + kh * XPITCH);
                float2 c = *(const float2*)(xrow + kh * XPITCH + 2);
                rin[kh][0] = a.x; rin[kh][1] = a.y;
                rin[kh][2] = c.x; rin[kh][3] = c.y;
            }
            const float* wp = &ws[ci * 9 * COUT_];
#pragma unroll
            for (int t = 0; t < 9; t++) {
                const int kh = t / 3, kw = t % 3;
                unsigned int u0 = __float_as_uint(rin[kh][kw]);
                unsigned int u1 = __float_as_uint(rin[kh][kw + 1]);
                unsigned long long ii0, ii1;
                DUP_F32X2(ii0, u0);
                DUP_F32X2(ii1, u1);
                // weight pairs: ulonglong2 load = LDS.128 = 4 weights = 2 pairs
                const ulonglong2* wq = (const ulonglong2*)(wp + t * COUT_);
#pragma unroll
                for (int j = 0; j < 8; j++) {
                    ulonglong2 w = wq[j];
                    FMA2(acc0[2 * j],     w.x, ii0);
                    FMA2(acc1[2 * j],     w.x, ii1);
                    FMA2(acc0[2 * j + 1], w.y, ii0);
                    FMA2(acc1[2 * j + 1], w.y, ii1);
                }
            }
        }
    }

    // --- epilogue: unpack, bias, store float2 per cout ---
#pragma unroll
    for (int k = 0; k < 16; k++) {
        float p0lo, p0hi, p1lo, p1hi;
        UNPACK2(p0lo, p0hi, acc0[k]);
        UNPACK2(p1lo, p1hi, acc1[k]);
        int co = 2 * k;
        float2 v0; v0.x = p0lo + bs[co];     v0.y = p1lo + bs[co];
        float2 v1; v1.x = p0hi + bs[co + 1]; v1.y = p1hi + bs[co + 1];
        *(float2*)&out[(((size_t)b * COUT_ + co)     * HW_ + oh) * HW_ + ow] = v0;
        *(float2*)&out[(((size_t)b * COUT_ + co + 1) * HW_ + oh) * HW_ + ow] = v1;
    }
}

// ---------------------------------------------------------------------------
extern "C" void kernel_launch(void* const* d_in, const int* in_sizes, int n_in,
                              void* d_out, int out_size) {
    const float* x  = (const float*)d_in[0];
    const float* rw = (const float*)d_in[1];
    const float* ew = (const float*)d_in[2];
    const float* eb = (const float*)d_in[3];
    float* out = (float*)d_out;

    condconv_prep_kernel<<<B_, 256>>>(rw, ew, eb);

    dim3 grid(HW_ / TILE_W, HW_ / TILE_H, B_);
    condconv_conv_kernel<<<grid, 256>>>(x, out);
}

// round 4
// speedup vs baseline: 1.9664x; 1.9421x over previous
#include <cuda_runtime.h>
#include <cstdint>

// CondConv2d via tf32 mma.sync.m16n8k8 implicit GEMM (sm_103 base target —
// tcgen05 is unavailable because the harness PTX targets sm_103, not sm_103a).
// B=16, CIN=32, H=W=256, COUT=32, 3x3 same-pad, 8 experts.
//
// GEMM per batch: D[pixel, co] = sum_k A[pixel, k] * W[co, k],  k=(ci,tap), K=288.
// CTA = 8h x 64w tile of one batch; 8 warps, warp = 1 h-row x 64 px x 32 co.
// k-chunks: 8 ci at a time; within a chunk k = tap*8 + ci_local -> kstep == tap.

#define B_    16
#define CIN_  32
#define HW_   256
#define COUT_ 32
#define NEXP  8
#define NPARAM 9216          // 32co * 32ci * 9

#define TILE_H 8
#define TILE_W 64
#define XP     68            // x smem pitch (floats): makes B-frag banks distinct
#define XROWS  10            // h-1 .. h+8
#define XCOLS  66            // w-1 .. w+64
#define KP     40            // weight smem pitch: makes A-frag banks distinct

__device__ float g_wt[B_ * NPARAM];   // [b][cichunk][tap][ci_local][co], tf32-rounded
__device__ float g_bias[B_ * COUT_];

__device__ __forceinline__ uint32_t f2tf32(float v) {
    uint32_t r;
    asm("cvt.rna.tf32.f32 %0, %1;" : "=r"(r) : "f"(v));
    return r;
}

__device__ __forceinline__ void mma_tf32(float c[4], const uint32_t a[4],
                                         uint32_t b0, uint32_t b1) {
    asm volatile(
        "mma.sync.aligned.m16n8k8.row.col.f32.tf32.tf32.f32 "
        "{%0,%1,%2,%3}, {%4,%5,%6,%7}, {%8,%9}, {%0,%1,%2,%3};"
        : "+f"(c[0]), "+f"(c[1]), "+f"(c[2]), "+f"(c[3])
        : "r"(a[0]), "r"(a[1]), "r"(a[2]), "r"(a[3]), "r"(b0), "r"(b1));
}

// ---------------------------------------------------------------------------
// Kernel 1: mix experts -> g_wt[b][cich][t][cil][co] (tf32), g_bias.
// ---------------------------------------------------------------------------
__global__ void condconv_prep_kernel(const float* __restrict__ rw,
                                     const float* __restrict__ ew,
                                     const float* __restrict__ eb) {
    int b = blockIdx.x;
    int tid = threadIdx.x;
    float r[NEXP];
#pragma unroll
    for (int e = 0; e < NEXP; e++) r[e] = rw[b * NEXP + e];

    for (int idx = tid; idx < NPARAM; idx += blockDim.x) {
        int cich = idx / 2304;
        int r1   = idx - cich * 2304;
        int t    = r1 >> 8;          // /256
        int r2   = r1 & 255;
        int cil  = r2 >> 5;
        int co   = r2 & 31;
        int ci   = cich * 8 + cil;
        int src  = co * (CIN_ * 9) + ci * 9 + t;   // source [co][ci][kh][kw]
        float s = 0.f;
#pragma unroll
        for (int e = 0; e < NEXP; e++) s += r[e] * ew[e * NPARAM + src];
        g_wt[b * NPARAM + idx] = __uint_as_float(f2tf32(s));
    }
    if (tid < COUT_) {
        float s = 0.f;
#pragma unroll
        for (int e = 0; e < NEXP; e++) s += r[e] * eb[e * COUT_ + tid];
        g_bias[b * COUT_ + tid] = s;
    }
}

// ---------------------------------------------------------------------------
// Kernel 2: tf32 mma.sync conv. Grid (4, 32, 16); 256 threads (8 warps).
// ---------------------------------------------------------------------------
__global__ __launch_bounds__(256, 2)
void condconv_mma_kernel(const float* __restrict__ x, float* __restrict__ out) {
    __shared__ float xs[8 * XROWS * XP];   // 5440 floats = 21760 B
    __shared__ float ws[72 * KP];          // 2880 floats = 11520 B
    __shared__ float bs[COUT_];

    const int b  = blockIdx.z;
    const int h0 = blockIdx.y * TILE_H;
    const int w0 = blockIdx.x * TILE_W;
    const int tid = threadIdx.x;
    const int wy  = tid >> 5;        // warp id = row within tile (0..7)
    const int lane = tid & 31;
    const int g   = lane >> 2;       // group id 0..7
    const int tig = lane & 3;        // thread in group 0..3

    const float* gw = g_wt + b * NPARAM;
    if (tid < COUT_) bs[tid] = g_bias[b * COUT_ + tid];

    float acc[2][8][4];
#pragma unroll
    for (int mt = 0; mt < 2; mt++)
#pragma unroll
        for (int nt = 0; nt < 8; nt++)
#pragma unroll
            for (int i = 0; i < 4; i++) acc[mt][nt][i] = 0.f;

#pragma unroll 1
    for (int cc = 0; cc < 4; cc++) {
        __syncthreads();

        // --- stage weights: ws[(t*8+cil)*KP + co] ---
        for (int i = tid; i < 2304; i += 256) {
            int t  = i >> 8;
            int r2 = i & 255;
            int cil = r2 >> 5;
            int co  = r2 & 31;
            ws[(t * 8 + cil) * KP + co] = gw[cc * 2304 + i];
        }

        // --- stage x tile: 8ci x 10row x 66col, zero halo, tf32-rounded ---
        for (int i = tid; i < 8 * XROWS * XCOLS; i += 256) {
            int ci  = i / (XROWS * XCOLS);
            int r1  = i - ci * (XROWS * XCOLS);
            int row = r1 / XCOLS;
            int col = r1 - row * XCOLS;
            int ih = h0 - 1 + row;
            int iw = w0 - 1 + col;
            float v = 0.f;
            if ((unsigned)ih < 256u && (unsigned)iw < 256u)
                v = x[(((size_t)b * CIN_ + (cc * 8 + ci)) * HW_ + ih) * HW_ + iw];
            xs[ci * (XROWS * XP) + row * XP + col] = __uint_as_float(f2tf32(v));
        }
        __syncthreads();

        // --- compute: 9 taps, kstep == tap ---
#pragma unroll
        for (int t = 0; t < 9; t++) {
            const int kh = t / 3, kw = t - 3 * kh;

            // A fragments (weights): a[mt] = W[co][k], k = t*8 + {tig, tig+4}
            uint32_t a[2][4];
            const uint32_t* wsu = (const uint32_t*)ws;
#pragma unroll
            for (int mt = 0; mt < 2; mt++) {
                int cob = mt * 16 + g;
                a[mt][0] = wsu[(t * 8 + tig)     * KP + cob];
                a[mt][1] = wsu[(t * 8 + tig)     * KP + cob + 8];
                a[mt][2] = wsu[(t * 8 + tig + 4) * KP + cob];
                a[mt][3] = wsu[(t * 8 + tig + 4) * KP + cob + 8];
            }

            // B fragments (x): b0 ci=tig, b1 ci=tig+4; col = pixel
            const uint32_t* xb = (const uint32_t*)
                (xs + (wy + kh) * XP + kw + g);
#pragma unroll
            for (int nt = 0; nt < 8; nt++) {
                uint32_t b0 = xb[tig       * (XROWS * XP) + nt * 8];
                uint32_t b1 = xb[(tig + 4) * (XROWS * XP) + nt * 8];
                mma_tf32(acc[0][nt], a[0], b0, b1);
                mma_tf32(acc[1][nt], a[1], b0, b1);
            }
        }
    }

    // --- epilogue: bias + store. c0/c1 -> (co, px=2*tig, 2*tig+1); c2/c3 -> co+8
    const int oh = h0 + wy;
#pragma unroll
    for (int mt = 0; mt < 2; mt++) {
#pragma unroll
        for (int nt = 0; nt < 8; nt++) {
            int co = mt * 16 + g;
            int pw = w0 + nt * 8 + 2 * tig;
            float2 v0, v1;
            v0.x = acc[mt][nt][0] + bs[co];
            v0.y = acc[mt][nt][1] + bs[co];
            v1.x = acc[mt][nt][2] + bs[co + 8];
            v1.y = acc[mt][nt][3] + bs[co + 8];
            *(float2*)&out[(((size_t)b * COUT_ + co)     * HW_ + oh) * HW_ + pw] = v0;
            *(float2*)&out[(((size_t)b * COUT_ + co + 8) * HW_ + oh) * HW_ + pw] = v1;
        }
    }
}

// ---------------------------------------------------------------------------
extern "C" void kernel_launch(void* const* d_in, const int* in_sizes, int n_in,
                              void* d_out, int out_size) {
    const float* x  = (const float*)d_in[0];
    const float* rw = (const float*)d_in[1];
    const float* ew = (const float*)d_in[2];
    const float* eb = (const float*)d_in[3];
    float* out = (float*)d_out;

    condconv_prep_kernel<<<B_, 256>>>(rw, ew, eb);

    dim3 grid(HW_ / TILE_W, HW_ / TILE_H, B_);
    condconv_mma_kernel<<<grid, 256>>>(x, out);
}

// round 5
// speedup vs baseline: 2.9035x; 1.4766x over previous
#include <cuda_runtime.h>
#include <cstdint>

// CondConv2d via tf32 mma.sync.m16n8k8 implicit GEMM, cp.async double-buffered.
// B=16, CIN=32, H=W=256, COUT=32, 3x3 same-pad, 8 experts.
// CTA = 8h x 64w x 32co of one batch; 512 threads / 16 warps; warp = 32px x 32co.
// k-chunks of 8 ci; within a chunk k = tap*8 + ci_local.

#define B_    16
#define CIN_  32
#define HW_   256
#define COUT_ 32
#define NEXP  8
#define NPARAM 9216

#define XP    68      // x smem pitch (floats) -> B-frag banks distinct
#define KP    40      // w smem pitch -> A-frag banks distinct

// smem layout (floats): [xs0 5440][ws0 2880][xs1 5440][ws1 2880][bias 32]
#define XS_F   5440                  // 8ci * 10rows * 68
#define WS_F   2880                  // 72 * 40
#define BUF_F  (XS_F + WS_F)         // 8320
#define BIAS_F (2 * BUF_F)           // 16640
#define SMEM_BYTES ((BIAS_F + 32) * 4)

// truncation-bias compensation: mma.sync tf32 truncates x's mantissa (RZ on
// magnitude); E[rel loss] = 2^-11 * E[1/m] ~= 3.38e-4. Pre-scale weights.
#define COMP 1.000338f

__device__ __align__(16) float g_wt[B_ * NPARAM];  // [b][cich][t][cil][co], tf32+comp
__device__ float g_bias[B_ * COUT_];

__device__ __forceinline__ uint32_t smem_u32(const void* p) {
    uint32_t a;
    asm("{ .reg .u64 t; cvta.to.shared.u64 t, %1; cvt.u32.u64 %0, t; }" : "=r"(a) : "l"(p));
    return a;
}
__device__ __forceinline__ uint32_t f2tf32(float v) {
    uint32_t r;
    asm("cvt.rna.tf32.f32 %0, %1;" : "=r"(r) : "f"(v));
    return r;
}
__device__ __forceinline__ void mma_tf32(float c[4], const uint32_t a[4],
                                         uint32_t b0, uint32_t b1) {
    asm volatile(
        "mma.sync.aligned.m16n8k8.row.col.f32.tf32.tf32.f32 "
        "{%0,%1,%2,%3}, {%4,%5,%6,%7}, {%8,%9}, {%0,%1,%2,%3};"
        : "+f"(c[0]), "+f"(c[1]), "+f"(c[2]), "+f"(c[3])
        : "r"(a[0]), "r"(a[1]), "r"(a[2]), "r"(a[3]), "r"(b0), "r"(b1));
}
__device__ __forceinline__ void cp_async4(uint32_t dst, const float* src, uint32_t sz) {
    asm volatile("cp.async.ca.shared.global [%0], [%1], 4, %2;"
                 :: "r"(dst), "l"(src), "r"(sz) : "memory");
}
__device__ __forceinline__ void cp_async16(uint32_t dst, const float* src) {
    asm volatile("cp.async.cg.shared.global [%0], [%1], 16;"
                 :: "r"(dst), "l"(src) : "memory");
}
#define CP_COMMIT() asm volatile("cp.async.commit_group;" ::: "memory")

// ---------------------------------------------------------------------------
// Kernel 1: mix experts -> g_wt[b][cich][t][cil][co] (tf32 * COMP), g_bias.
// Grid (16, 4): blockIdx.y = ci-chunk.
// ---------------------------------------------------------------------------
__global__ void condconv_prep_kernel(const float* __restrict__ rw,
                                     const float* __restrict__ ew,
                                     const float* __restrict__ eb) {
    int b = blockIdx.x, q = blockIdx.y;
    int tid = threadIdx.x;
    float r[NEXP];
#pragma unroll
    for (int e = 0; e < NEXP; e++) r[e] = rw[b * NEXP + e];

    for (int i = tid; i < 2304; i += 256) {
        int t   = i >> 8;
        int r2  = i & 255;
        int cil = r2 >> 5;
        int co  = r2 & 31;
        int ci  = q * 8 + cil;
        int src = co * (CIN_ * 9) + ci * 9 + t;
        float s = 0.f;
#pragma unroll
        for (int e = 0; e < NEXP; e++) s += r[e] * ew[e * NPARAM + src];
        g_wt[b * NPARAM + q * 2304 + i] = __uint_as_float(f2tf32(s * COMP));
    }
    if (q == 0 && tid < COUT_) {
        float s = 0.f;
#pragma unroll
        for (int e = 0; e < NEXP; e++) s += r[e] * eb[e * COUT_ + tid];
        g_bias[b * COUT_ + tid] = s;
    }
}

// ---------------------------------------------------------------------------
// staging: cp.async one ci-chunk (x tile + weights) into one smem buffer
// ---------------------------------------------------------------------------
__device__ __forceinline__ void stage_chunk(uint32_t sx, uint32_t sw,
                                            const float* __restrict__ xsrc,
                                            const float* __restrict__ wsrc,
                                            int h0, int w0, int tid) {
    // x: 8ci x 10rows x 66cols, zero halo
    for (int i = tid; i < 8 * 10 * 66; i += 512) {
        int ci  = i / 660;
        int r1  = i - ci * 660;
        int row = r1 / 66;
        int col = r1 - row * 66;
        int ih = h0 - 1 + row;
        int iw = w0 - 1 + col;
        bool ok = ((unsigned)ih < 256u) && ((unsigned)iw < 256u);
        const float* src = xsrc + (size_t)ci * (HW_ * HW_) + (ok ? (ih * HW_ + iw) : 0);
        cp_async4(sx + (uint32_t)(ci * (10 * XP) + row * XP + col) * 4, src, ok ? 4u : 0u);
    }
    // w: 72 rows x 32 co, 16B vectors
    for (int i = tid; i < 576; i += 512) {
        int k  = i >> 3;
        int c4 = (i & 7) * 4;
        cp_async16(sw + (uint32_t)(k * KP + c4) * 4, wsrc + k * 32 + c4);
    }
}

// ---------------------------------------------------------------------------
// Kernel 2: conv. Grid (4, 32, 16); 512 threads, 16 warps.
// ---------------------------------------------------------------------------
__global__ __launch_bounds__(512, 2)
void condconv_mma_kernel(const float* __restrict__ x, float* __restrict__ out) {
    extern __shared__ float sm[];
    const uint32_t sbase = smem_u32(sm);

    const int b  = blockIdx.z;
    const int h0 = blockIdx.y * 8;
    const int w0 = blockIdx.x * 64;
    const int tid = threadIdx.x;
    const int wid = tid >> 5, lane = tid & 31;
    const int g = lane >> 2, tig = lane & 3;
    const int wy = wid >> 1, wh = wid & 1;   // row 0..7, w-half 0..1

    const float* gw = g_wt + b * NPARAM;
    const float* xb = x + (size_t)b * CIN_ * HW_ * HW_;

    if (tid < COUT_) sm[BIAS_F + tid] = g_bias[b * COUT_ + tid];

    float acc[2][4][4];
#pragma unroll
    for (int mt = 0; mt < 2; mt++)
#pragma unroll
        for (int nt = 0; nt < 4; nt++)
#pragma unroll
            for (int i = 0; i < 4; i++) acc[mt][nt][i] = 0.f;

    // prologue: stage chunk 0 into buffer 0
    stage_chunk(sbase, sbase + XS_F * 4, xb, gw, h0, w0, tid);
    CP_COMMIT();

#pragma unroll 1
    for (int cc = 0; cc < 4; cc++) {
        if (cc < 3) {
            uint32_t boff = (uint32_t)(((cc + 1) & 1) * BUF_F) * 4;
            stage_chunk(sbase + boff, sbase + boff + XS_F * 4,
                        xb + (size_t)(cc + 1) * 8 * HW_ * HW_,
                        gw + (cc + 1) * 2304, h0, w0, tid);
            CP_COMMIT();
            asm volatile("cp.async.wait_group 1;" ::: "memory");
        } else {
            asm volatile("cp.async.wait_group 0;" ::: "memory");
        }
        __syncthreads();

        const float* xs = sm + (cc & 1) * BUF_F;
        const uint32_t* wsu = (const uint32_t*)(xs + XS_F);
        const uint32_t* xsu = (const uint32_t*)xs;

#pragma unroll
        for (int t = 0; t < 9; t++) {
            const int kh = t / 3, kw = t - 3 * kh;
            uint32_t a[2][4];
#pragma unroll
            for (int mt = 0; mt < 2; mt++) {
                int cob = mt * 16 + g;
                a[mt][0] = wsu[(t * 8 + tig)     * KP + cob];
                a[mt][1] = wsu[(t * 8 + tig)     * KP + cob + 8];
                a[mt][2] = wsu[(t * 8 + tig + 4) * KP + cob];
                a[mt][3] = wsu[(t * 8 + tig + 4) * KP + cob + 8];
            }
            const uint32_t* xf = xsu + (wy + kh) * XP + kw + wh * 32 + g + tig * (10 * XP);
#pragma unroll
            for (int nt = 0; nt < 4; nt++) {
                uint32_t b0 = xf[nt * 8];
                uint32_t b1 = xf[nt * 8 + 4 * (10 * XP)];
                mma_tf32(acc[0][nt], a[0], b0, b1);
                mma_tf32(acc[1][nt], a[1], b0, b1);
            }
        }
        if (cc < 3) __syncthreads();   // buffer about to be overwritten next iter
    }

    // epilogue
    const float* bs = sm + BIAS_F;
    const int oh = h0 + wy;
#pragma unroll
    for (int mt = 0; mt < 2; mt++) {
#pragma unroll
        for (int nt = 0; nt < 4; nt++) {
            int co = mt * 16 + g;
            int pw = w0 + wh * 32 + nt * 8 + 2 * tig;
            float2 v0, v1;
            v0.x = acc[mt][nt][0] + bs[co];
            v0.y = acc[mt][nt][1] + bs[co];
            v1.x = acc[mt][nt][2] + bs[co + 8];
            v1.y = acc[mt][nt][3] + bs[co + 8];
            *(float2*)&out[(((size_t)b * COUT_ + co)     * HW_ + oh) * HW_ + pw] = v0;
            *(float2*)&out[(((size_t)b * COUT_ + co + 8) * HW_ + oh) * HW_ + pw] = v1;
        }
    }
}

// ---------------------------------------------------------------------------
extern "C" void kernel_launch(void* const* d_in, const int* in_sizes, int n_in,
                              void* d_out, int out_size) {
    const float* x  = (const float*)d_in[0];
    const float* rw = (const float*)d_in[1];
    const float* ew = (const float*)d_in[2];
    const float* eb = (const float*)d_in[3];
    float* out = (float*)d_out;

    condconv_prep_kernel<<<dim3(B_, 4), 256>>>(rw, ew, eb);

    cudaFuncSetAttribute(condconv_mma_kernel,
                         cudaFuncAttributeMaxDynamicSharedMemorySize, SMEM_BYTES);
    dim3 grid(HW_ / 64, HW_ / 8, B_);
    condconv_mma_kernel<<<grid, 512, SMEM_BYTES>>>(x, out);
}

// round 6
// speedup vs baseline: 4.1794x; 1.4394x over previous
#include <cuda_runtime.h>
#include <cstdint>

// CondConv2d via tf32 mma.sync.m16n8k8 implicit GEMM.
// R6: A-fragments stored in fragment order (2x LDS.128/tap), vectorized
// cp.async staging, zero per-tap address ALU.
// CTA = 8h x 64w x 32co of one batch; 512 threads; warp = 32px x 32co.

#define B_    16
#define CIN_  32
#define HW_   256
#define COUT_ 32
#define NEXP  8
#define NPARAM 9216

#define XP    76      // x smem pitch: 760 % 32 == 24 -> B-frag banks distinct
// x tile cols: smem col 4+d == global iw w0+d ; halo-left col 3, halo-right col 68
#define XS_F   6080                  // 8ci * 10rows * 76
#define WS_F   2304                  // 9 taps * 256 (fragment order)
#define BUF_F  (XS_F + WS_F)         // 8384
#define BIAS_F (2 * BUF_F)           // 16768
#define SMEM_BYTES ((BIAS_F + 32) * 4)

// compensate tf32 truncation of x inside mma.sync (E[rel loss] ~ 3.38e-4)
#define COMP 1.000338f

__device__ __align__(16) float g_wt[B_ * NPARAM];  // [b][cc][t][half][lane][4]
__device__ float g_bias[B_ * COUT_];

__device__ __forceinline__ uint32_t smem_u32(const void* p) {
    uint32_t a;
    asm("{ .reg .u64 t; cvta.to.shared.u64 t, %1; cvt.u32.u64 %0, t; }" : "=r"(a) : "l"(p));
    return a;
}
__device__ __forceinline__ uint32_t f2tf32(float v) {
    uint32_t r;
    asm("cvt.rna.tf32.f32 %0, %1;" : "=r"(r) : "f"(v));
    return r;
}
__device__ __forceinline__ void mma_tf32(float c[4], const uint32_t a[4],
                                         uint32_t b0, uint32_t b1) {
    asm volatile(
        "mma.sync.aligned.m16n8k8.row.col.f32.tf32.tf32.f32 "
        "{%0,%1,%2,%3}, {%4,%5,%6,%7}, {%8,%9}, {%0,%1,%2,%3};"
        : "+f"(c[0]), "+f"(c[1]), "+f"(c[2]), "+f"(c[3])
        : "r"(a[0]), "r"(a[1]), "r"(a[2]), "r"(a[3]), "r"(b0), "r"(b1));
}
__device__ __forceinline__ void cp_async4(uint32_t dst, const float* src, uint32_t sz) {
    asm volatile("cp.async.ca.shared.global [%0], [%1], 4, %2;"
                 :: "r"(dst), "l"(src), "r"(sz) : "memory");
}
__device__ __forceinline__ void cp_async16z(uint32_t dst, const float* src, uint32_t sz) {
    asm volatile("cp.async.cg.shared.global [%0], [%1], 16, %2;"
                 :: "r"(dst), "l"(src), "r"(sz) : "memory");
}
#define CP_COMMIT() asm volatile("cp.async.commit_group;" ::: "memory")

// ---------------------------------------------------------------------------
// Kernel 1: mix experts -> fragment-ordered g_wt (tf32 * COMP), g_bias.
// g_wt float index: ((b*4+cc)*9 + t)*256 + half*128 + lane*4 + jj
//   lane=(g,tig); half=mt; jj: co = mt*16+g+(jj&1)*8, k = tig+(jj>>1)*4
// ---------------------------------------------------------------------------
__global__ void condconv_prep_kernel(const float* __restrict__ rw,
                                     const float* __restrict__ ew,
                                     const float* __restrict__ eb) {
    int b = blockIdx.x, q = blockIdx.y;
    int tid = threadIdx.x;
    float r[NEXP];
#pragma unroll
    for (int e = 0; e < NEXP; e++) r[e] = rw[b * NEXP + e];

    for (int i = tid; i < 2304; i += 256) {
        int t    = i >> 8;
        int rr   = i & 255;
        int half = rr >> 7;
        int lane = (rr >> 2) & 31;
        int jj   = rr & 3;
        int g = lane >> 2, tig = lane & 3;
        int co = half * 16 + g + (jj & 1) * 8;
        int ci = q * 8 + tig + (jj >> 1) * 4;
        int src = co * (CIN_ * 9) + ci * 9 + t;
        float s = 0.f;
#pragma unroll
        for (int e = 0; e < NEXP; e++) s += r[e] * ew[e * NPARAM + src];
        g_wt[b * NPARAM + q * 2304 + i] = __uint_as_float(f2tf32(s * COMP));
    }
    if (q == 0 && tid < COUT_) {
        float s = 0.f;
#pragma unroll
        for (int e = 0; e < NEXP; e++) s += r[e] * eb[e * COUT_ + tid];
        g_bias[b * COUT_ + tid] = s;
    }
}

// ---------------------------------------------------------------------------
// staging one ci-chunk: interior via 16B cp.async, halo cols scalar, weights 16B
// ---------------------------------------------------------------------------
__device__ __forceinline__ void stage_chunk(uint32_t sx, uint32_t sw,
                                            const float* __restrict__ xsrc,
                                            const float* __restrict__ wsrc,
                                            int h0, int w0, int tid) {
    // interior: 8ci x 10rows x 16 float4 (cols w0..w0+63 -> smem cols 4..67)
    for (int i = tid; i < 1280; i += 512) {
        int ci  = i / 160;
        int r1  = i - ci * 160;
        int row = r1 >> 4;
        int v   = r1 & 15;
        int ih  = h0 - 1 + row;
        bool ok = (unsigned)ih < 256u;
        const float* src = xsrc + (size_t)ci * (HW_ * HW_) + (ok ? ih * HW_ : 0) + w0 + v * 4;
        cp_async16z(sx + (uint32_t)(ci * (10 * XP) + row * XP + 4 + v * 4) * 4,
                    src, ok ? 16u : 0u);
    }
    // halo: 8ci x 10rows x 2 cols (w0-1 -> col 3, w0+64 -> col 68)
    for (int i = tid; i < 160; i += 512) {
        int ci   = i / 20;
        int r1   = i - ci * 20;
        int row  = r1 >> 1;
        int side = r1 & 1;
        int ih = h0 - 1 + row;
        int iw = side ? (w0 + 64) : (w0 - 1);
        bool ok = ((unsigned)ih < 256u) && ((unsigned)iw < 256u);
        const float* src = xsrc + (size_t)ci * (HW_ * HW_) + (ok ? (ih * HW_ + iw) : 0);
        cp_async4(sx + (uint32_t)(ci * (10 * XP) + row * XP + (side ? 68 : 3)) * 4,
                  src, ok ? 4u : 0u);
    }
    // weights: 2304 floats = 576 float4, contiguous fragment order
    for (int i = tid; i < 576; i += 512)
        cp_async16z(sw + (uint32_t)i * 16, wsrc + i * 4, 16u);
}

// ---------------------------------------------------------------------------
// Kernel 2: conv. Grid (4, 32, 16); 512 threads, 16 warps.
// ---------------------------------------------------------------------------
__global__ __launch_bounds__(512, 2)
void condconv_mma_kernel(const float* __restrict__ x, float* __restrict__ out) {
    extern __shared__ float sm[];
    const uint32_t sbase = smem_u32(sm);

    const int b  = blockIdx.z;
    const int h0 = blockIdx.y * 8;
    const int w0 = blockIdx.x * 64;
    const int tid = threadIdx.x;
    const int wid = tid >> 5, lane = tid & 31;
    const int g = lane >> 2, tig = lane & 3;
    const int wy = wid >> 1, wh = wid & 1;

    const float* gw = g_wt + b * NPARAM;
    const float* xb = x + (size_t)b * CIN_ * HW_ * HW_;

    if (tid < COUT_) sm[BIAS_F + tid] = g_bias[b * COUT_ + tid];

    float acc[2][4][4];
#pragma unroll
    for (int mt = 0; mt < 2; mt++)
#pragma unroll
        for (int nt = 0; nt < 4; nt++)
#pragma unroll
            for (int i = 0; i < 4; i++) acc[mt][nt][i] = 0.f;

    stage_chunk(sbase, sbase + XS_F * 4, xb, gw, h0, w0, tid);
    CP_COMMIT();

#pragma unroll 1
    for (int cc = 0; cc < 4; cc++) {
        if (cc < 3) {
            uint32_t boff = (uint32_t)(((cc + 1) & 1) * BUF_F) * 4;
            stage_chunk(sbase + boff, sbase + boff + XS_F * 4,
                        xb + (size_t)(cc + 1) * 8 * HW_ * HW_,
                        gw + (cc + 1) * 2304, h0, w0, tid);
            CP_COMMIT();
            asm volatile("cp.async.wait_group 1;" ::: "memory");
        } else {
            asm volatile("cp.async.wait_group 0;" ::: "memory");
        }
        __syncthreads();

        const float* xs = sm + (cc & 1) * BUF_F;
        // A fragments: uint4 at  wf + t*64 (half0) / + t*64+32 (half1), per lane
        const uint4* wf = (const uint4*)(xs + XS_F) + lane;
        // B base: pixel col for (kw,nt): smem col = wh*32 + g + 3 + kw + nt*8
        const uint32_t* xf = (const uint32_t*)xs + wh * 32 + g + 3 + tig * (10 * XP);

#pragma unroll
        for (int t = 0; t < 9; t++) {
            const int kh = t / 3, kw = t - 3 * kh;
            uint4 q0 = wf[t * 64];
            uint4 q1 = wf[t * 64 + 32];
            uint32_t a0[4] = {q0.x, q0.y, q0.z, q0.w};
            uint32_t a1[4] = {q1.x, q1.y, q1.z, q1.w};
            const uint32_t* xt = xf + (wy + kh) * XP + kw;
#pragma unroll
            for (int nt = 0; nt < 4; nt++) {
                uint32_t b0 = xt[nt * 8];
                uint32_t b1 = xt[nt * 8 + 4 * (10 * XP)];
                mma_tf32(acc[0][nt], a0, b0, b1);
                mma_tf32(acc[1][nt], a1, b0, b1);
            }
        }
        if (cc < 3) __syncthreads();
    }

    const float* bs = sm + BIAS_F;
    const int oh = h0 + wy;
#pragma unroll
    for (int mt = 0; mt < 2; mt++) {
#pragma unroll
        for (int nt = 0; nt < 4; nt++) {
            int co = mt * 16 + g;
            int pw = w0 + wh * 32 + nt * 8 + 2 * tig;
            float2 v0, v1;
            v0.x = acc[mt][nt][0] + bs[co];
            v0.y = acc[mt][nt][1] + bs[co];
            v1.x = acc[mt][nt][2] + bs[co + 8];
            v1.y = acc[mt][nt][3] + bs[co + 8];
            *(float2*)&out[(((size_t)b * COUT_ + co)     * HW_ + oh) * HW_ + pw] = v0;
            *(float2*)&out[(((size_t)b * COUT_ + co + 8) * HW_ + oh) * HW_ + pw] = v1;
        }
    }
}

// ---------------------------------------------------------------------------
extern "C" void kernel_launch(void* const* d_in, const int* in_sizes, int n_in,
                              void* d_out, int out_size) {
    const float* x  = (const float*)d_in[0];
    const float* rw = (const float*)d_in[1];
    const float* ew = (const float*)d_in[2];
    const float* eb = (const float*)d_in[3];
    float* out = (float*)d_out;

    condconv_prep_kernel<<<dim3(B_, 4), 256>>>(rw, ew, eb);

    cudaFuncSetAttribute(condconv_mma_kernel,
                         cudaFuncAttributeMaxDynamicSharedMemorySize, SMEM_BYTES);
    dim3 grid(HW_ / 64, HW_ / 8, B_);
    condconv_mma_kernel<<<grid, 512, SMEM_BYTES>>>(x, out);
}

// round 7
// speedup vs baseline: 4.4636x; 1.0680x over previous
#include <cuda_runtime.h>
#include <cstdint>

// CondConv2d via tf32 mma.sync.m16n8k8 implicit GEMM.
// R7: 2-output-row register blocking with kh reuse of B fragments
// (149 B smem traffic per MMA, down from 256 B).
// CTA = 8h x 64w x 32co of one batch; 256 threads / 8 warps;
// warp = 2h x 32px x 32co.

#define B_    16
#define CIN_  32
#define HW_   256
#define COUT_ 32
#define NEXP  8
#define NPARAM 9216

#define XP    76      // x smem pitch: 760 % 32 == 24 -> B-frag banks distinct
#define XS_F   6080                  // 8ci * 10rows * 76
#define WS_F   2304                  // 9 taps * 256 (fragment order)
#define BUF_F  (XS_F + WS_F)         // 8384
#define BIAS_F (2 * BUF_F)           // 16768
#define SMEM_BYTES ((BIAS_F + 32) * 4)

// compensate tf32 truncation of x inside mma.sync (E[rel loss] ~ 3.38e-4)
#define COMP 1.000338f

__device__ __align__(16) float g_wt[B_ * NPARAM];  // [b][cc][t][half][lane][4]
__device__ float g_bias[B_ * COUT_];

__device__ __forceinline__ uint32_t smem_u32(const void* p) {
    uint32_t a;
    asm("{ .reg .u64 t; cvta.to.shared.u64 t, %1; cvt.u32.u64 %0, t; }" : "=r"(a) : "l"(p));
    return a;
}
__device__ __forceinline__ uint32_t f2tf32(float v) {
    uint32_t r;
    asm("cvt.rna.tf32.f32 %0, %1;" : "=r"(r) : "f"(v));
    return r;
}
__device__ __forceinline__ void mma_tf32(float c[4], const uint32_t a[4],
                                         uint32_t b0, uint32_t b1) {
    asm volatile(
        "mma.sync.aligned.m16n8k8.row.col.f32.tf32.tf32.f32 "
        "{%0,%1,%2,%3}, {%4,%5,%6,%7}, {%8,%9}, {%0,%1,%2,%3};"
        : "+f"(c[0]), "+f"(c[1]), "+f"(c[2]), "+f"(c[3])
        : "r"(a[0]), "r"(a[1]), "r"(a[2]), "r"(a[3]), "r"(b0), "r"(b1));
}
__device__ __forceinline__ void cp_async4(uint32_t dst, const float* src, uint32_t sz) {
    asm volatile("cp.async.ca.shared.global [%0], [%1], 4, %2;"
                 :: "r"(dst), "l"(src), "r"(sz) : "memory");
}
__device__ __forceinline__ void cp_async16z(uint32_t dst, const float* src, uint32_t sz) {
    asm volatile("cp.async.cg.shared.global [%0], [%1], 16, %2;"
                 :: "r"(dst), "l"(src), "r"(sz) : "memory");
}
#define CP_COMMIT() asm volatile("cp.async.commit_group;" ::: "memory")

// ---------------------------------------------------------------------------
// Kernel 1: mix experts -> fragment-ordered g_wt (tf32 * COMP), g_bias.
// g_wt float index: ((b*4+cc)*9 + t)*256 + half*128 + lane*4 + jj
//   lane=(g,tig); half=mt; jj: co = mt*16+g+(jj&1)*8, k = tig+(jj>>1)*4
// ---------------------------------------------------------------------------
__global__ void condconv_prep_kernel(const float* __restrict__ rw,
                                     const float* __restrict__ ew,
                                     const float* __restrict__ eb) {
    int b = blockIdx.x, q = blockIdx.y;
    int tid = threadIdx.x;
    float r[NEXP];
#pragma unroll
    for (int e = 0; e < NEXP; e++) r[e] = rw[b * NEXP + e];

    for (int i = tid; i < 2304; i += 256) {
        int t    = i >> 8;
        int rr   = i & 255;
        int half = rr >> 7;
        int lane = (rr >> 2) & 31;
        int jj   = rr & 3;
        int g = lane >> 2, tig = lane & 3;
        int co = half * 16 + g + (jj & 1) * 8;
        int ci = q * 8 + tig + (jj >> 1) * 4;
        int src = co * (CIN_ * 9) + ci * 9 + t;
        float s = 0.f;
#pragma unroll
        for (int e = 0; e < NEXP; e++) s += r[e] * ew[e * NPARAM + src];
        g_wt[b * NPARAM + q * 2304 + i] = __uint_as_float(f2tf32(s * COMP));
    }
    if (q == 0 && tid < COUT_) {
        float s = 0.f;
#pragma unroll
        for (int e = 0; e < NEXP; e++) s += r[e] * eb[e * COUT_ + tid];
        g_bias[b * COUT_ + tid] = s;
    }
}

// ---------------------------------------------------------------------------
// staging one ci-chunk (256-thread stride)
// ---------------------------------------------------------------------------
__device__ __forceinline__ void stage_chunk(uint32_t sx, uint32_t sw,
                                            const float* __restrict__ xsrc,
                                            const float* __restrict__ wsrc,
                                            int h0, int w0, int tid) {
    // interior: 8ci x 10rows x 16 float4 (global cols w0..w0+63 -> smem 4..67)
    for (int i = tid; i < 1280; i += 256) {
        int ci  = i / 160;
        int r1  = i - ci * 160;
        int row = r1 >> 4;
        int v   = r1 & 15;
        int ih  = h0 - 1 + row;
        bool ok = (unsigned)ih < 256u;
        const float* src = xsrc + (size_t)ci * (HW_ * HW_) + (ok ? ih * HW_ : 0) + w0 + v * 4;
        cp_async16z(sx + (uint32_t)(ci * (10 * XP) + row * XP + 4 + v * 4) * 4,
                    src, ok ? 16u : 0u);
    }
    // halo: 8ci x 10rows x 2 cols (w0-1 -> col 3, w0+64 -> col 68)
    for (int i = tid; i < 160; i += 256) {
        int ci   = i / 20;
        int r1   = i - ci * 20;
        int row  = r1 >> 1;
        int side = r1 & 1;
        int ih = h0 - 1 + row;
        int iw = side ? (w0 + 64) : (w0 - 1);
        bool ok = ((unsigned)ih < 256u) && ((unsigned)iw < 256u);
        const float* src = xsrc + (size_t)ci * (HW_ * HW_) + (ok ? (ih * HW_ + iw) : 0);
        cp_async4(sx + (uint32_t)(ci * (10 * XP) + row * XP + (side ? 68 : 3)) * 4,
                  src, ok ? 4u : 0u);
    }
    // weights: 576 float4, contiguous fragment order
    for (int i = tid; i < 576; i += 256)
        cp_async16z(sw + (uint32_t)i * 16, wsrc + i * 4, 16u);
}

// ---------------------------------------------------------------------------
// Kernel 2: conv. Grid (4, 32, 16); 256 threads, 8 warps.
// warp: wy = wid>>1 -> output rows h0+2*wy, h0+2*wy+1 ; wh = wid&1 -> w half.
// ---------------------------------------------------------------------------
__global__ __launch_bounds__(256, 2)
void condconv_mma_kernel(const float* __restrict__ x, float* __restrict__ out) {
    extern __shared__ float sm[];
    const uint32_t sbase = smem_u32(sm);

    const int b  = blockIdx.z;
    const int h0 = blockIdx.y * 8;
    const int w0 = blockIdx.x * 64;
    const int tid = threadIdx.x;
    const int wid = tid >> 5, lane = tid & 31;
    const int g = lane >> 2, tig = lane & 3;
    const int wy = wid >> 1, wh = wid & 1;

    const float* gw = g_wt + b * NPARAM;
    const float* xb = x + (size_t)b * CIN_ * HW_ * HW_;

    if (tid < COUT_) sm[BIAS_F + tid] = g_bias[b * COUT_ + tid];

    float acc[2][2][4][4];   // [row][mt][nt][4]
#pragma unroll
    for (int r = 0; r < 2; r++)
#pragma unroll
        for (int mt = 0; mt < 2; mt++)
#pragma unroll
            for (int nt = 0; nt < 4; nt++)
#pragma unroll
                for (int i = 0; i < 4; i++) acc[r][mt][nt][i] = 0.f;

    stage_chunk(sbase, sbase + XS_F * 4, xb, gw, h0, w0, tid);
    CP_COMMIT();

#pragma unroll 1
    for (int cc = 0; cc < 4; cc++) {
        if (cc < 3) {
            uint32_t boff = (uint32_t)(((cc + 1) & 1) * BUF_F) * 4;
            stage_chunk(sbase + boff, sbase + boff + XS_F * 4,
                        xb + (size_t)(cc + 1) * 8 * HW_ * HW_,
                        gw + (cc + 1) * 2304, h0, w0, tid);
            CP_COMMIT();
            asm volatile("cp.async.wait_group 1;" ::: "memory");
        } else {
            asm volatile("cp.async.wait_group 0;" ::: "memory");
        }
        __syncthreads();

        const float* xs = sm + (cc & 1) * BUF_F;
        const uint4* wf = (const uint4*)(xs + XS_F) + lane;
        // B base: x smem row for xr: (2*wy + xr); col = wh*32+g+3+kw+8nt
        const uint32_t* xf = (const uint32_t*)xs + (2 * wy) * XP
                           + wh * 32 + g + 3 + tig * (10 * XP);

#pragma unroll
        for (int kw = 0; kw < 3; kw++) {
            // load B fragments for the 4 x-rows once
            uint32_t B0[4][4], B1[4][4];
#pragma unroll
            for (int xr = 0; xr < 4; xr++) {
                const uint32_t* xt = xf + xr * XP + kw;
#pragma unroll
                for (int nt = 0; nt < 4; nt++) {
                    B0[xr][nt] = xt[nt * 8];
                    B1[xr][nt] = xt[nt * 8 + 4 * (10 * XP)];
                }
            }
#pragma unroll
            for (int kh = 0; kh < 3; kh++) {
                const int t = kh * 3 + kw;
                uint4 q0 = wf[t * 64];
                uint4 q1 = wf[t * 64 + 32];
                uint32_t a0[4] = {q0.x, q0.y, q0.z, q0.w};
                uint32_t a1[4] = {q1.x, q1.y, q1.z, q1.w};
#pragma unroll
                for (int r = 0; r < 2; r++) {
                    const int xr = r + kh;
#pragma unroll
                    for (int nt = 0; nt < 4; nt++) {
                        mma_tf32(acc[r][0][nt], a0, B0[xr][nt], B1[xr][nt]);
                        mma_tf32(acc[r][1][nt], a1, B0[xr][nt], B1[xr][nt]);
                    }
                }
            }
        }
        if (cc < 3) __syncthreads();
    }

    const float* bs = sm + BIAS_F;
#pragma unroll
    for (int r = 0; r < 2; r++) {
        const int oh = h0 + 2 * wy + r;
#pragma unroll
        for (int mt = 0; mt < 2; mt++) {
#pragma unroll
            for (int nt = 0; nt < 4; nt++) {
                int co = mt * 16 + g;
                int pw = w0 + wh * 32 + nt * 8 + 2 * tig;
                float2 v0, v1;
                v0.x = acc[r][mt][nt][0] + bs[co];
                v0.y = acc[r][mt][nt][1] + bs[co];
                v1.x = acc[r][mt][nt][2] + bs[co + 8];
                v1.y = acc[r][mt][nt][3] + bs[co + 8];
                *(float2*)&out[(((size_t)b * COUT_ + co)     * HW_ + oh) * HW_ + pw] = v0;
                *(float2*)&out[(((size_t)b * COUT_ + co + 8) * HW_ + oh) * HW_ + pw] = v1;
            }
        }
    }
}

// ---------------------------------------------------------------------------
extern "C" void kernel_launch(void* const* d_in, const int* in_sizes, int n_in,
                              void* d_out, int out_size) {
    const float* x  = (const float*)d_in[0];
    const float* rw = (const float*)d_in[1];
    const float* ew = (const float*)d_in[2];
    const float* eb = (const float*)d_in[3];
    float* out = (float*)d_out;

    condconv_prep_kernel<<<dim3(B_, 4), 256>>>(rw, ew, eb);

    cudaFuncSetAttribute(condconv_mma_kernel,
                         cudaFuncAttributeMaxDynamicSharedMemorySize, SMEM_BYTES);
    dim3 grid(HW_ / 64, HW_ / 8, B_);
    condconv_mma_kernel<<<grid, 256, SMEM_BYTES>>>(x, out);
}

// round 8
// speedup vs baseline: 4.6512x; 1.0420x over previous
#include <cuda_runtime.h>
#include <cstdint>

// CondConv2d via fp16 mma.sync.m16n8k16 implicit GEMM (f32 accumulate).
// R8: half the MMA count of the tf32-k8 version at equal mantissa width.
// CTA = 8h x 64w x 32co of one batch; 256 threads / 8 warps;
// warp = 2h x 32px x 32co. K-chunks: 2 x 16 ci; per tap one K=16 MMA step.

#define B_    16
#define CIN_  32
#define HW_   256
#define COUT_ 32
#define NEXP  8
#define NPARAM 9216

// ---- smem layout in 4-byte units ----
#define RAWP   72                     // raw f32 staging pitch (floats)
#define SCR_U  0                      // raw: 16 planes x 10 rows x 72 = 11520
#define XPH    68                     // packed f16x2 pitch (words)
#define XSH0_U 11520                  // 8 jpairs x 10 rows x 68 = 5440 words
#define XSH1_U 16960
#define WS0_U  22400                  // 2304 words (fragment-ordered f16 pairs)
#define WS1_U  24704
#define BIAS_U 27008                  // 32 floats
#define SMEM_U 27040
#define SMEM_BYTES (SMEM_U * 4)       // 108160 B

__device__ uint32_t g_wt_h[B_ * 4608];   // [b][cc][t][mt][lane][4] f16x2 words
__device__ float    g_bias[B_ * COUT_];

__device__ __forceinline__ uint32_t smem_u32(const void* p) {
    uint32_t a;
    asm("{ .reg .u64 t; cvta.to.shared.u64 t, %1; cvt.u32.u64 %0, t; }" : "=r"(a) : "l"(p));
    return a;
}
// pack: lo half = lo, hi half = hi  (PTX: first src -> hi)
__device__ __forceinline__ uint32_t pack_f16x2(float hi, float lo) {
    uint32_t d;
    asm("cvt.rn.f16x2.f32 %0, %1, %2;" : "=r"(d) : "f"(hi), "f"(lo));
    return d;
}
__device__ __forceinline__ void mma_f16(float c[4], const uint32_t a[4],
                                        uint32_t b0, uint32_t b1) {
    asm volatile(
        "mma.sync.aligned.m16n8k16.row.col.f32.f16.f16.f32 "
        "{%0,%1,%2,%3}, {%4,%5,%6,%7}, {%8,%9}, {%0,%1,%2,%3};"
        : "+f"(c[0]), "+f"(c[1]), "+f"(c[2]), "+f"(c[3])
        : "r"(a[0]), "r"(a[1]), "r"(a[2]), "r"(a[3]), "r"(b0), "r"(b1));
}
__device__ __forceinline__ void cp_async4(uint32_t dst, const void* src, uint32_t sz) {
    asm volatile("cp.async.ca.shared.global [%0], [%1], 4, %2;"
                 :: "r"(dst), "l"(src), "r"(sz) : "memory");
}
__device__ __forceinline__ void cp_async16z(uint32_t dst, const void* src, uint32_t sz) {
    asm volatile("cp.async.cg.shared.global [%0], [%1], 16, %2;"
                 :: "r"(dst), "l"(src), "r"(sz) : "memory");
}
#define CP_COMMIT() asm volatile("cp.async.commit_group;" ::: "memory")
#define CP_WAIT0()  asm volatile("cp.async.wait_group 0;" ::: "memory")

// ---------------------------------------------------------------------------
// Kernel 1: mix experts -> fragment-ordered fp16 weights + bias.
// word index (per b): ((cc*9 + t)*2 + mt)*32*4 + lane*4 + w
//   w: a0..a3 of m16n8k16 A-frag. co = mt*16 + g + (w&1)*8;
//   ci = cc*16 + 2*tig + (w>>1)*8, halves {ci, ci+1}.
// ---------------------------------------------------------------------------
__global__ void condconv_prep_kernel(const float* __restrict__ rw,
                                     const float* __restrict__ ew,
                                     const float* __restrict__ eb) {
    int b = blockIdx.x, cc = blockIdx.y;
    int tid = threadIdx.x;
    float r[NEXP];
#pragma unroll
    for (int e = 0; e < NEXP; e++) r[e] = rw[b * NEXP + e];

    for (int i = tid; i < 2304; i += 256) {
        int t    = i >> 8;
        int r2   = i & 255;
        int mt   = r2 >> 7;
        int lane = (r2 >> 2) & 31;
        int w    = r2 & 3;
        int g = lane >> 2, tig = lane & 3;
        int co = mt * 16 + g + (w & 1) * 8;
        int ci = cc * 16 + 2 * tig + (w >> 1) * 8;
        int src_lo = co * (CIN_ * 9) + ci * 9 + t;
        float s_lo = 0.f, s_hi = 0.f;
#pragma unroll
        for (int e = 0; e < NEXP; e++) {
            s_lo += r[e] * ew[e * NPARAM + src_lo];
            s_hi += r[e] * ew[e * NPARAM + src_lo + 9];   // ci+1
        }
        g_wt_h[(b * 2 + cc) * 2304 + i] = pack_f16x2(s_hi, s_lo);
    }
    if (cc == 0 && tid < COUT_) {
        float s = 0.f;
#pragma unroll
        for (int e = 0; e < NEXP; e++) s += r[e] * eb[e * COUT_ + tid];
        g_bias[b * COUT_ + tid] = s;
    }
}

// ---------------------------------------------------------------------------
// staging: raw f32 x (16 planes) -> scratch ; f16 weights -> ws buffer
// raw col rc <-> iw = w0 + (rc - 4); used rc 3..68; zero halo via src-size 0.
// ---------------------------------------------------------------------------
__device__ __forceinline__ void stage_chunk(uint32_t scr, uint32_t swu,
                                            const float* __restrict__ xsrc,
                                            const uint32_t* __restrict__ wsrc,
                                            int h0, int w0, int tid) {
    for (int i = tid; i < 2560; i += 256) {            // interior 16B
        int pl  = i / 160;
        int r1  = i - pl * 160;
        int row = r1 >> 4;
        int v   = r1 & 15;
        int ih  = h0 - 1 + row;
        bool ok = (unsigned)ih < 256u;
        const float* src = xsrc + (size_t)pl * (HW_ * HW_) + (ok ? ih * HW_ : 0) + w0 + v * 4;
        cp_async16z(scr + (uint32_t)(pl * (10 * RAWP) + row * RAWP + 4 + v * 4) * 4,
                    src, ok ? 16u : 0u);
    }
    for (int i = tid; i < 320; i += 256) {             // halo scalars
        int pl   = i / 20;
        int r1   = i - pl * 20;
        int row  = r1 >> 1;
        int side = r1 & 1;
        int ih = h0 - 1 + row;
        int iw = side ? (w0 + 64) : (w0 - 1);
        bool ok = ((unsigned)ih < 256u) && ((unsigned)iw < 256u);
        const float* src = xsrc + (size_t)pl * (HW_ * HW_) + (ok ? (ih * HW_ + iw) : 0);
        cp_async4(scr + (uint32_t)(pl * (10 * RAWP) + row * RAWP + (side ? 68 : 3)) * 4,
                  src, ok ? 4u : 0u);
    }
    for (int i = tid; i < 576; i += 256)               // weights: 576 x 16B
        cp_async16z(swu + (uint32_t)i * 16, wsrc + i * 4, 16u);
}

// convert: scratch f32 -> packed f16x2 over adjacent ci (j = ci/2)
// xsh col c (0..65) <-> iw = w0-1+c ; raw col = c+3.
__device__ __forceinline__ void convert_chunk(const float* scr, uint32_t* xsh, int tid) {
    for (int i = tid; i < 5280; i += 256) {
        int j   = i / 660;
        int r1  = i - j * 660;
        int row = r1 / 66;
        int c   = r1 - row * 66;
        float f0 = scr[(2 * j)     * (10 * RAWP) + row * RAWP + c + 3];
        float f1 = scr[(2 * j + 1) * (10 * RAWP) + row * RAWP + c + 3];
        xsh[j * (10 * XPH) + row * XPH + c] = pack_f16x2(f1, f0);
    }
}

// compute one 16-ci chunk
__device__ __forceinline__ void compute_chunk(const uint32_t* xsh, const uint32_t* ws,
                                              float acc[2][2][4][4],
                                              int lane, int g, int tig, int wy, int wh) {
    const uint4* wf = (const uint4*)ws + lane;
    const uint32_t* xf = xsh + (2 * wy) * XPH + wh * 32 + g + tig * (10 * XPH);

#pragma unroll
    for (int kw = 0; kw < 3; kw++) {
        uint32_t B0[4][4], B1[4][4];
#pragma unroll
        for (int xr = 0; xr < 4; xr++) {
            const uint32_t* xt = xf + xr * XPH + kw;
#pragma unroll
            for (int nt = 0; nt < 4; nt++) {
                B0[xr][nt] = xt[nt * 8];
                B1[xr][nt] = xt[nt * 8 + 4 * (10 * XPH)];
            }
        }
#pragma unroll
        for (int kh = 0; kh < 3; kh++) {
            const int t = kh * 3 + kw;
            uint4 q0 = wf[(t * 2) * 32];
            uint4 q1 = wf[(t * 2 + 1) * 32];
            uint32_t a0[4] = {q0.x, q0.y, q0.z, q0.w};
            uint32_t a1[4] = {q1.x, q1.y, q1.z, q1.w};
#pragma unroll
            for (int r = 0; r < 2; r++) {
                const int xr = r + kh;
#pragma unroll
                for (int nt = 0; nt < 4; nt++) {
                    mma_f16(acc[r][0][nt], a0, B0[xr][nt], B1[xr][nt]);
                    mma_f16(acc[r][1][nt], a1, B0[xr][nt], B1[xr][nt]);
                }
            }
        }
    }
}

// ---------------------------------------------------------------------------
// Kernel 2: conv. Grid (4, 32, 16); 256 threads, 8 warps.
// ---------------------------------------------------------------------------
__global__ __launch_bounds__(256, 2)
void condconv_mma_kernel(const float* __restrict__ x, float* __restrict__ out) {
    extern __shared__ float sm[];
    const uint32_t sbase = smem_u32(sm);

    const int b  = blockIdx.z;
    const int h0 = blockIdx.y * 8;
    const int w0 = blockIdx.x * 64;
    const int tid = threadIdx.x;
    const int lane = tid & 31, wid = tid >> 5;
    const int g = lane >> 2, tig = lane & 3;
    const int wy = wid >> 1, wh = wid & 1;

    const uint32_t* gw = g_wt_h + b * 4608;
    const float* xb = x + (size_t)b * CIN_ * HW_ * HW_;

    if (tid < COUT_) sm[BIAS_U + tid] = g_bias[b * COUT_ + tid];

    float acc[2][2][4][4];
#pragma unroll
    for (int r = 0; r < 2; r++)
#pragma unroll
        for (int mt = 0; mt < 2; mt++)
#pragma unroll
            for (int nt = 0; nt < 4; nt++)
#pragma unroll
                for (int i = 0; i < 4; i++) acc[r][mt][nt][i] = 0.f;

    // chunk 0: stage -> convert
    stage_chunk(sbase + SCR_U * 4, sbase + WS0_U * 4, xb, gw, h0, w0, tid);
    CP_COMMIT();
    CP_WAIT0();
    __syncthreads();
    convert_chunk(sm + SCR_U, (uint32_t*)(sm + XSH0_U), tid);
    __syncthreads();

    // chunk 1 staging overlaps chunk 0 compute
    stage_chunk(sbase + SCR_U * 4, sbase + WS1_U * 4,
                xb + (size_t)16 * HW_ * HW_, gw + 2304, h0, w0, tid);
    CP_COMMIT();

    compute_chunk((const uint32_t*)(sm + XSH0_U), (const uint32_t*)(sm + WS0_U),
                  acc, lane, g, tig, wy, wh);

    CP_WAIT0();
    __syncthreads();
    convert_chunk(sm + SCR_U, (uint32_t*)(sm + XSH1_U), tid);
    __syncthreads();

    compute_chunk((const uint32_t*)(sm + XSH1_U), (const uint32_t*)(sm + WS1_U),
                  acc, lane, g, tig, wy, wh);

    // epilogue
    const float* bs = sm + BIAS_U;
#pragma unroll
    for (int r = 0; r < 2; r++) {
        const int oh = h0 + 2 * wy + r;
#pragma unroll
        for (int mt = 0; mt < 2; mt++) {
#pragma unroll
            for (int nt = 0; nt < 4; nt++) {
                int co = mt * 16 + g;
                int pw = w0 + wh * 32 + nt * 8 + 2 * tig;
                float2 v0, v1;
                v0.x = acc[r][mt][nt][0] + bs[co];
                v0.y = acc[r][mt][nt][1] + bs[co];
                v1.x = acc[r][mt][nt][2] + bs[co + 8];
                v1.y = acc[r][mt][nt][3] + bs[co + 8];
                *(float2*)&out[(((size_t)b * COUT_ + co)     * HW_ + oh) * HW_ + pw] = v0;
                *(float2*)&out[(((size_t)b * COUT_ + co + 8) * HW_ + oh) * HW_ + pw] = v1;
            }
        }
    }
}

// ---------------------------------------------------------------------------
extern "C" void kernel_launch(void* const* d_in, const int* in_sizes, int n_in,
                              void* d_out, int out_size) {
    const float* x  = (const float*)d_in[0];
    const float* rw = (const float*)d_in[1];
    const float* ew = (const float*)d_in[2];
    const float* eb = (const float*)d_in[3];
    float* out = (float*)d_out;

    condconv_prep_kernel<<<dim3(B_, 2), 256>>>(rw, ew, eb);

    cudaFuncSetAttribute(condconv_mma_kernel,
                         cudaFuncAttributeMaxDynamicSharedMemorySize, SMEM_BYTES);
    dim3 grid(HW_ / 64, HW_ / 8, B_);
    condconv_mma_kernel<<<grid, 256, SMEM_BYTES>>>(x, out);
}